// round 7
// baseline (speedup 1.0000x reference)
#include <cuda_runtime.h>

// ---------------------------------------------------------------------------
// BackwardConv2D: forward SAME 3x3 conv, flipped kernel, Cin/Cout swapped.
// 512 images (2 tensors x B=8 x N=32) of 32x32x64 fp32. n innermost.
// R7: n-pair packing. Lane = (n-pair 0..15) x (ci-half 0..1). Window values
// arrive packed via LDG.64 (no dup movs); weights pre-duplicated to u64 in
// gmem by the transform kernel. Cuts L1 traffic ~2.6x per FFMA2 (R6 ncu:
// L1 78.4% binding before fma 63.7%).
// ---------------------------------------------------------------------------

#define NPLANES 16                    // (b,t): b in [0,8), t in {u=0, l=1}
#define PLANE   (34*34*64*32)         // padded plane floats
#define HALO_PER_PLANE 270336
#define SRC_PER_PLANE 2097152

typedef unsigned long long u64t;

__device__ float g_pad[(size_t)NPLANES * PLANE];      // ~151.5 MB scratch
__device__ u64t  g_wt2[64 * 9 * 64];                  // [co][tap][ci] dup'd (w,w)
__device__ float g_bpart[NPLANES][64][32];

__device__ __forceinline__ u64t dup2(float v) {
    u64t r; asm("mov.b64 %0, {%1, %1};" : "=l"(r) : "f"(v)); return r;
}
__device__ __forceinline__ void ffma2(u64t& d, u64t a, u64t b) {
    asm("fma.rn.f32x2 %0, %1, %2, %0;" : "+l"(d) : "l"(a), "l"(b));
}

// ---------------------------------------------------------------------------
// 1) Zero only the halo ring of each padded plane.
// ---------------------------------------------------------------------------
__global__ void halo_zero_kernel() {
    int j = blockIdx.x * 256 + threadIdx.x;
    if (j >= NPLANES * HALO_PER_PLANE) return;
    int plane = j / HALO_PER_PLANE;
    int r = j % HALO_PER_PLANE;
    int off;
    if (r < 2 * 34 * 2048) {
        int wr = (r < 34 * 2048) ? 0 : 33;
        int rem = r % (34 * 2048);
        off = wr * (34 * 2048) + rem;
    } else {
        int q = r - 2 * 34 * 2048;
        int row = q / 4096;
        int s = q % 4096;
        off = (row + 1) * (34 * 2048) + ((s < 2048) ? s : (33 * 2048 + (s - 2048)));
    }
    g_pad[(size_t)plane * PLANE + off] = 0.f;
}

// ---------------------------------------------------------------------------
// 2) Weight transform + pre-dup: g_wt2[(co*9+t)*64+ci] = (w,w) where
//    w = kernel[(8-t)*4096 + ci*64 + co].
// ---------------------------------------------------------------------------
__global__ void wtrans_kernel(const float* __restrict__ ker) {
    int j = blockIdx.x * 256 + threadIdx.x;
    if (j >= 64 * 9 * 64) return;
    int ci = j & 63;
    int t  = (j >> 6) % 9;
    int co = j / 576;
    g_wt2[j] = dup2(ker[(8 - t) * 4096 + ci * 64 + co]);
}

// ---------------------------------------------------------------------------
// 3) Pad inputs into g_pad planes + fused deterministic bias partial sums.
// ---------------------------------------------------------------------------
__global__ void __launch_bounds__(256) pad_kernel(
    const float* __restrict__ wu, const float* __restrict__ wl,
    const float* __restrict__ bias)
{
    __shared__ float bs[64];
    __shared__ float red[8][32];
    int plane = blockIdx.y;
    int b = plane >> 1, t = plane & 1;
    const float* src = (t ? wl : wu) + (size_t)b * SRC_PER_PLANE;
    if (threadIdx.x < 64) bs[threadIdx.x] = bias[threadIdx.x];
    __syncthreads();
    int wid = threadIdx.x >> 5, lane = threadIdx.x & 31;
    float* dstp = g_pad + (size_t)plane * PLANE;
    float psum = 0.f;
    int base = blockIdx.x * 32768;
    #pragma unroll 4
    for (int k = 0; k < 128; k++) {
        int e = base + k * 256 + threadIdx.x;
        float v = src[e];
        int f  = e >> 5;
        int co = f & 63;
        int s  = f >> 6;
        int wr = (s >> 5) + 1, wc = (s & 31) + 1;
        dstp[((wr * 34 + wc) * 64 + co) * 32 + (e & 31)] = v;
        psum += v * bs[co];
    }
    red[wid][lane] = psum;
    __syncthreads();
    if (wid == 0) {
        float s2 = red[0][lane];
        #pragma unroll
        for (int ww = 1; ww < 8; ww++) s2 += red[ww][lane];
        g_bpart[plane][blockIdx.x][lane] = s2;
    }
}

// ---------------------------------------------------------------------------
// 4) Main conv. Warp: 2x2 px x 16 ci x 32 n. lane = np(0..15) + 16*cihalf.
//    Window loads: LDG.64 n-pairs (half-warps broadcast). Weights: pre-dup'd
//    u64. Rolling 2-row window ring. Block = 8 warps = 4 px-quads x 2
//    ci-groups(16). Grid = (64 tiles, 2 ci32-halves, 16 planes). 2 CTAs/SM.
// ---------------------------------------------------------------------------
__global__ void __launch_bounds__(256, 2) conv_kernel(float* __restrict__ out) {
    const int plane  = blockIdx.z;
    const int b      = plane >> 1, t = plane & 1;
    const int tile   = blockIdx.x;
    const int tr = tile >> 3, tc = tile & 7;
    const int wid  = threadIdx.x >> 5, lane = threadIdx.x & 31;
    const int pg   = wid >> 1;              // 0..3 pixel quad
    const int cig  = wid & 1;               // 0..1 ci16-group
    const int np   = lane & 15;             // n-pair index
    const int cih  = lane >> 4;             // ci-half within group
    const int r0 = tr * 4 + (pg >> 1) * 2;
    const int c0 = tc * 4 + (pg & 1) * 2;
    const int cibase = blockIdx.y * 32 + cig * 16 + cih * 8;   // 8 ci per lane

    const float* pin = g_pad + (size_t)plane * PLANE
                     + (size_t)(r0 * 34 + c0) * 2048 + 2 * np;
    const u64t* wbase = g_wt2 + cibase;

    u64t acc[4][8];                          // [px][ci] packed n-pair
    #pragma unroll
    for (int i = 0; i < 4; i++)
        #pragma unroll
        for (int j = 0; j < 8; j++) acc[i][j] = 0ull;

    for (int co = 0; co < 64; ++co) {
        u64t vd[2][4];                       // rolling 2-row window ring
        #pragma unroll
        for (int dc = 0; dc < 4; dc++) {
            vd[0][dc] = __ldg((const u64t*)(pin + (0 * 34 + dc) * 2048));
            vd[1][dc] = __ldg((const u64t*)(pin + (1 * 34 + dc) * 2048));
        }
        #pragma unroll
        for (int dh = 0; dh < 3; dh++) {
            #pragma unroll
            for (int dw = 0; dw < 3; dw++) {
                const u64t* wp = wbase + (co * 9 + dh * 3 + dw) * 64;
                u64t w[8];
                #pragma unroll
                for (int j = 0; j < 8; j++) w[j] = __ldg(wp + j);
                // out(pr,pc) += vd[row pr+dh][pc+dw] * w  ; ring slot (pr+dh)&1
                #pragma unroll
                for (int pr = 0; pr < 2; pr++) {
                    #pragma unroll
                    for (int pc = 0; pc < 2; pc++) {
                        u64t a = vd[(pr + dh) & 1][pc + dw];
                        #pragma unroll
                        for (int j = 0; j < 8; j++)
                            ffma2(acc[pr * 2 + pc][j], a, w[j]);
                    }
                }
            }
            // roll in next row (r0+dh+2) replacing oldest
            if (dh < 2) {
                #pragma unroll
                for (int dc = 0; dc < 4; dc++)
                    vd[dh & 1][dc] =
                        __ldg((const u64t*)(pin + ((dh + 2) * 34 + dc) * 2048));
            }
        }
        pin += 32;  // next co
    }

    // store n-pairs: out idx = base + ((h*32+w)*64 + ci)*32 + 2*np  (u64)
    size_t obase = (t ? (size_t)16777472 : (size_t)0) + (size_t)b * 2097152
                 + 2 * np;
    #pragma unroll
    for (int pr = 0; pr < 2; pr++) {
        #pragma unroll
        for (int pc = 0; pc < 2; pc++) {
            int h = r0 + pr, w = c0 + pc;
            size_t po = obase + (size_t)((h * 32 + w) * 64 + cibase) * 32;
            #pragma unroll
            for (int j = 0; j < 8; j++)
                *(u64t*)(out + po + (size_t)j * 32) = acc[pr * 2 + pc][j];
        }
    }
}

// ---------------------------------------------------------------------------
// 5) Bias finalize (fixed-order deterministic sum).
// ---------------------------------------------------------------------------
__global__ void bias_fin_kernel(const float* __restrict__ bu,
                                const float* __restrict__ bl,
                                float* __restrict__ out) {
    int plane = threadIdx.x >> 5, lane = threadIdx.x & 31;
    if (plane >= NPLANES) return;
    float s = 0.f;
    #pragma unroll 8
    for (int c = 0; c < 64; c++) s += g_bpart[plane][c][lane];
    int b = plane >> 1, t = plane & 1;
    s += (t ? bl : bu)[b * 32 + lane];
    out[(t ? 33554688 : 16777216) + b * 32 + lane] = s;
}

// ---------------------------------------------------------------------------
// Launch. Inputs: x(unused), w_out_u, b_out_u, w_out_l, b_out_l, kernel, bias.
// Output: [w_u | b_u | w_l | b_l] fp32.
// ---------------------------------------------------------------------------
extern "C" void kernel_launch(void* const* d_in, const int* in_sizes, int n_in,
                              void* d_out, int out_size) {
    (void)in_sizes; (void)n_in; (void)out_size;
    const float* w_u  = (const float*)d_in[1];
    const float* b_u  = (const float*)d_in[2];
    const float* w_l  = (const float*)d_in[3];
    const float* b_l  = (const float*)d_in[4];
    const float* ker  = (const float*)d_in[5];
    const float* bias = (const float*)d_in[6];
    float* out = (float*)d_out;

    halo_zero_kernel<<<(NPLANES * HALO_PER_PLANE + 255) / 256, 256>>>();
    wtrans_kernel<<<(64 * 9 * 64 + 255) / 256, 256>>>(ker);
    pad_kernel<<<dim3(64, 16), 256>>>(w_u, w_l, bias);
    conv_kernel<<<dim3(64, 2, 16), 256>>>(out);
    bias_fin_kernel<<<1, 512>>>(b_u, b_l, out);
}

// round 12
// speedup vs baseline: 1.5793x; 1.5793x over previous
#include <cuda_runtime.h>

// ---------------------------------------------------------------------------
// BackwardConv2D: forward SAME 3x3 conv, flipped kernel, Cin/Cout swapped.
// 512 images (2 tensors x B=8 x N=32) of 32x32x64 fp32. lane == n.
// R8 = R6 (best, 820.7us: fma 63.7%, L1 78.4%) + smem weight staging:
// the 18 warp-uniform weight LDG.128s per co-iter (~2/3 of L1 wavefronts)
// become LDS.128 broadcasts. Window loads / FFMA2 order unchanged.
// ---------------------------------------------------------------------------

#define NPLANES 16                    // (b,t): b in [0,8), t in {u=0, l=1}
#define PLANE   (34*34*64*32)         // padded plane floats
#define HALO_PER_PLANE 270336
#define SRC_PER_PLANE 2097152

__device__ float g_pad[(size_t)NPLANES * PLANE];      // ~151.5 MB scratch
__device__ float g_wt[64 * 9 * 64];                   // [co][tap][ci]
__device__ float g_bpart[NPLANES][64][32];

typedef unsigned long long u64t;

__device__ __forceinline__ u64t dup2(float v) {
    u64t r; asm("mov.b64 %0, {%1, %1};" : "=l"(r) : "f"(v)); return r;
}
__device__ __forceinline__ void ffma2(u64t& d, u64t a, u64t b) {
    asm("fma.rn.f32x2 %0, %1, %2, %0;" : "+l"(d) : "l"(a), "l"(b));
}
__device__ __forceinline__ void unpack2(u64t a, float& lo, float& hi) {
    asm("mov.b64 {%0, %1}, %2;" : "=f"(lo), "=f"(hi) : "l"(a));
}

// ---------------------------------------------------------------------------
// 1) Zero only the halo ring of each padded plane.
// ---------------------------------------------------------------------------
__global__ void halo_zero_kernel() {
    int j = blockIdx.x * 256 + threadIdx.x;
    if (j >= NPLANES * HALO_PER_PLANE) return;
    int plane = j / HALO_PER_PLANE;
    int r = j % HALO_PER_PLANE;
    int off;
    if (r < 2 * 34 * 2048) {
        int wr = (r < 34 * 2048) ? 0 : 33;
        int rem = r % (34 * 2048);
        off = wr * (34 * 2048) + rem;
    } else {
        int q = r - 2 * 34 * 2048;
        int row = q / 4096;
        int s = q % 4096;
        off = (row + 1) * (34 * 2048) + ((s < 2048) ? s : (33 * 2048 + (s - 2048)));
    }
    g_pad[(size_t)plane * PLANE + off] = 0.f;
}

// ---------------------------------------------------------------------------
// 2) Weight transform: g_wt[(co*9+t)*64+ci] = kernel[(8-t)*4096 + ci*64 + co]
// ---------------------------------------------------------------------------
__global__ void wtrans_kernel(const float* __restrict__ ker) {
    int j = blockIdx.x * 256 + threadIdx.x;
    if (j >= 64 * 9 * 64) return;
    int ci = j & 63;
    int t  = (j >> 6) % 9;
    int co = j / 576;
    g_wt[j] = ker[(8 - t) * 4096 + ci * 64 + co];
}

// ---------------------------------------------------------------------------
// 3) Pad inputs into g_pad planes + fused deterministic bias partial sums.
// ---------------------------------------------------------------------------
__global__ void __launch_bounds__(256) pad_kernel(
    const float* __restrict__ wu, const float* __restrict__ wl,
    const float* __restrict__ bias)
{
    __shared__ float bs[64];
    __shared__ float red[8][32];
    int plane = blockIdx.y;
    int b = plane >> 1, t = plane & 1;
    const float* src = (t ? wl : wu) + (size_t)b * SRC_PER_PLANE;
    if (threadIdx.x < 64) bs[threadIdx.x] = bias[threadIdx.x];
    __syncthreads();
    int wid = threadIdx.x >> 5, lane = threadIdx.x & 31;
    float* dstp = g_pad + (size_t)plane * PLANE;
    float psum = 0.f;
    int base = blockIdx.x * 32768;
    #pragma unroll 4
    for (int k = 0; k < 128; k++) {
        int e = base + k * 256 + threadIdx.x;
        float v = src[e];
        int f  = e >> 5;
        int co = f & 63;
        int s  = f >> 6;
        int wr = (s >> 5) + 1, wc = (s & 31) + 1;
        dstp[((wr * 34 + wc) * 64 + co) * 32 + (e & 31)] = v;
        psum += v * bs[co];
    }
    red[wid][lane] = psum;
    __syncthreads();
    if (wid == 0) {
        float s2 = red[0][lane];
        #pragma unroll
        for (int ww = 1; ww < 8; ww++) s2 += red[ww][lane];
        g_bpart[plane][blockIdx.x][lane] = s2;
    }
}

// ---------------------------------------------------------------------------
// 4) Main conv: FFMA2 hot loop, 2x2 px x 8 ci per warp, 2 CTAs/SM.
//    Weights staged in smem (36KB: 64 co x 9 taps x 16 ci), read via
//    LDS.128 broadcast. Block = 8 warps = 4 px-quads x 2 ci-groups.
//    Grid = (64 tiles, 4 ci-quarters, 16 planes).
// ---------------------------------------------------------------------------
__global__ void __launch_bounds__(256, 2) conv_kernel(float* __restrict__ out) {
    __shared__ __align__(16) float sw[64 * 9 * 16];   // [co][tap][16 ci]

    const int plane  = blockIdx.z;
    const int b      = plane >> 1, t = plane & 1;
    const int ciq    = blockIdx.y;        // 0..3 (16 ci per block)
    const int tile   = blockIdx.x;
    const int tr = tile >> 3, tc = tile & 7;
    const int wid  = threadIdx.x >> 5, lane = threadIdx.x & 31;
    const int pg   = wid >> 1;            // 0..3 pixel quad
    const int cig  = wid & 1;             // 0..1 ci group
    const int r0 = tr * 4 + (pg >> 1) * 2;
    const int c0 = tc * 4 + (pg & 1) * 2;
    const int cibase = ciq * 16 + cig * 8;

    // stage weight slice: sw[(co*9+t)*16 + i] = g_wt[(co*9+t)*64 + ciq*16 + i]
    #pragma unroll
    for (int i = threadIdx.x; i < 64 * 9 * 16; i += 256)
        sw[i] = g_wt[(i >> 4) * 64 + ciq * 16 + (i & 15)];
    __syncthreads();

    const float* pin = g_pad + (size_t)plane * PLANE + (size_t)(r0 * 34 + c0) * 2048 + lane;
    const float* swp0 = sw + cig * 8;

    u64t acc[4][4];
    #pragma unroll
    for (int i = 0; i < 4; i++)
        #pragma unroll
        for (int j = 0; j < 4; j++) acc[i][j] = 0ull;

    for (int co = 0; co < 64; ++co) {
        // 4x4 window (per-lane n), dup to packed f32x2
        u64t vd[4][4];
        #pragma unroll
        for (int dr = 0; dr < 4; dr++)
            #pragma unroll
            for (int dc = 0; dc < 4; dc++)
                vd[dr][dc] = dup2(__ldg(pin + (dr * 34 + dc) * 2048));

        const float* wp = swp0 + co * 144;          // (co*9+0)*16
        #pragma unroll
        for (int dh = 0; dh < 3; dh++) {
            #pragma unroll
            for (int dw = 0; dw < 3; dw++) {
                const int tt = dh * 3 + dw;
                ulonglong2 wA = *reinterpret_cast<const ulonglong2*>(wp + tt * 16);
                ulonglong2 wB = *reinterpret_cast<const ulonglong2*>(wp + tt * 16 + 4);
                #pragma unroll
                for (int pr = 0; pr < 2; pr++) {
                    #pragma unroll
                    for (int pc = 0; pc < 2; pc++) {
                        u64t a = vd[pr + dh][pc + dw];
                        ffma2(acc[pr * 2 + pc][0], a, wA.x);
                        ffma2(acc[pr * 2 + pc][1], a, wA.y);
                        ffma2(acc[pr * 2 + pc][2], a, wB.x);
                        ffma2(acc[pr * 2 + pc][3], a, wB.y);
                    }
                }
            }
        }
        pin += 32;  // next co
    }

    // store: w_u at 0, w_l at 16777472 (after b_u)
    size_t obase = (t ? (size_t)16777472 : (size_t)0) + (size_t)b * 2097152 + lane;
    #pragma unroll
    for (int pr = 0; pr < 2; pr++) {
        #pragma unroll
        for (int pc = 0; pc < 2; pc++) {
            int h = r0 + pr, w = c0 + pc;
            size_t po = obase + (size_t)((h * 32 + w) * 64) * 32;
            #pragma unroll
            for (int cp = 0; cp < 4; cp++) {
                float lo, hi;
                unpack2(acc[pr * 2 + pc][cp], lo, hi);
                int ci = cibase + 2 * cp;
                out[po + (size_t)ci * 32]       = lo;
                out[po + (size_t)(ci + 1) * 32] = hi;
            }
        }
    }
}

// ---------------------------------------------------------------------------
// 5) Bias finalize (fixed-order deterministic sum).
// ---------------------------------------------------------------------------
__global__ void bias_fin_kernel(const float* __restrict__ bu,
                                const float* __restrict__ bl,
                                float* __restrict__ out) {
    int plane = threadIdx.x >> 5, lane = threadIdx.x & 31;
    if (plane >= NPLANES) return;
    float s = 0.f;
    #pragma unroll 8
    for (int c = 0; c < 64; c++) s += g_bpart[plane][c][lane];
    int b = plane >> 1, t = plane & 1;
    s += (t ? bl : bu)[b * 32 + lane];
    out[(t ? 33554688 : 16777216) + b * 32 + lane] = s;
}

// ---------------------------------------------------------------------------
// Launch. Inputs: x(unused), w_out_u, b_out_u, w_out_l, b_out_l, kernel, bias.
// Output: [w_u | b_u | w_l | b_l] fp32.
// ---------------------------------------------------------------------------
extern "C" void kernel_launch(void* const* d_in, const int* in_sizes, int n_in,
                              void* d_out, int out_size) {
    (void)in_sizes; (void)n_in; (void)out_size;
    const float* w_u  = (const float*)d_in[1];
    const float* b_u  = (const float*)d_in[2];
    const float* w_l  = (const float*)d_in[3];
    const float* b_l  = (const float*)d_in[4];
    const float* ker  = (const float*)d_in[5];
    const float* bias = (const float*)d_in[6];
    float* out = (float*)d_out;

    halo_zero_kernel<<<(NPLANES * HALO_PER_PLANE + 255) / 256, 256>>>();
    wtrans_kernel<<<(64 * 9 * 64 + 255) / 256, 256>>>(ker);
    pad_kernel<<<dim3(64, 16), 256>>>(w_u, w_l, bias);
    conv_kernel<<<dim3(64, 4, 16), 256>>>(out);
    bias_fin_kernel<<<1, 512>>>(b_u, b_l, out);
}